// round 5
// baseline (speedup 1.0000x reference)
#include <cuda_runtime.h>
#include <cuda_bf16.h>
#include <cstdint>
#include <cstddef>

// Problem constants
#define BB   64
#define TT   2048
#define DD   256
#define HH   256
#define OO   256
#define FH   1024   // 4*H

// Phase-2 partitioning: 8 batch groups x 16 hidden groups = 128 CTAs
#define NGRP 8      // batch groups
#define GB   8      // batches per group
#define RC   16     // hidden-group CTAs per batch group
#define HU   16     // hidden units per CTA

// Device-global scratch (allocation-free per harness rules)
__device__ float    g_G[(size_t)BB * TT * FH];    // 536 MB: x@Wih + bh
__device__ float    g_Hall[(size_t)BB * TT * HH]; // 134 MB: every h_t
__device__ unsigned g_ctr[NGRP];

// ---------------------------------------------------------------------------
// Reset the per-group step counters (must run at the start of every launch)
// ---------------------------------------------------------------------------
__global__ void init_kernel() {
    if (threadIdx.x < NGRP) g_ctr[threadIdx.x] = 0u;
}

// ---------------------------------------------------------------------------
// fp32 GEMM: C[M,N] = A[M,K] @ B[K,N] + bias[N]
// 128x128 tile, 256 threads, 8x8 micro-tile, K-chunks of 16.
// Requires M%128==0, N%128==0, K%16==0.
// ---------------------------------------------------------------------------
__global__ __launch_bounds__(256, 2) void gemm_kernel(
    const float* __restrict__ A, const float* __restrict__ B,
    const float* __restrict__ bias, float* __restrict__ C,
    int M, int N, int K)
{
    __shared__ float As[16][132];   // A tile transposed: [k][row], padded
    __shared__ float Bs[16][132];   // B tile: [k][col], padded

    const int tid  = threadIdx.x;
    const int m0   = blockIdx.y * 128;
    const int n0   = blockIdx.x * 128;
    const int ty   = tid >> 4, tx = tid & 15;
    const int arow = tid >> 1, aseg = (tid & 1) * 8;
    const int brow = tid >> 4, bcol = (tid & 15) * 4;

    float acc[8][8];
#pragma unroll
    for (int i = 0; i < 8; i++)
#pragma unroll
        for (int j = 0; j < 8; j++) acc[i][j] = 0.f;

    for (int k0 = 0; k0 < K; k0 += 16) {
        float4 av0 = *(const float4*)&A[(size_t)(m0 + arow) * K + k0 + aseg];
        float4 av1 = *(const float4*)&A[(size_t)(m0 + arow) * K + k0 + aseg + 4];
        float4 bv0 = *(const float4*)&B[(size_t)(k0 + brow) * N + n0 + bcol];
        float4 bv1 = *(const float4*)&B[(size_t)(k0 + brow) * N + n0 + bcol + 64];

        As[aseg + 0][arow] = av0.x; As[aseg + 1][arow] = av0.y;
        As[aseg + 2][arow] = av0.z; As[aseg + 3][arow] = av0.w;
        As[aseg + 4][arow] = av1.x; As[aseg + 5][arow] = av1.y;
        As[aseg + 6][arow] = av1.z; As[aseg + 7][arow] = av1.w;
        *(float4*)&Bs[brow][bcol]      = bv0;
        *(float4*)&Bs[brow][bcol + 64] = bv1;
        __syncthreads();

#pragma unroll
        for (int k = 0; k < 16; k++) {
            float a[8], b[8];
            *(float4*)&a[0] = *(const float4*)&As[k][ty * 8];
            *(float4*)&a[4] = *(const float4*)&As[k][ty * 8 + 4];
            *(float4*)&b[0] = *(const float4*)&Bs[k][tx * 8];
            *(float4*)&b[4] = *(const float4*)&Bs[k][tx * 8 + 4];
#pragma unroll
            for (int i = 0; i < 8; i++)
#pragma unroll
                for (int j = 0; j < 8; j++)
                    acc[i][j] = fmaf(a[i], b[j], acc[i][j]);
        }
        __syncthreads();
    }

#pragma unroll
    for (int i = 0; i < 8; i++) {
        size_t row = (size_t)(m0 + ty * 8 + i);
#pragma unroll
        for (int j = 0; j < 8; j += 4) {
            int col = n0 + tx * 8 + j;
            float4 v;
            v.x = acc[i][j + 0] + bias[col + 0];
            v.y = acc[i][j + 1] + bias[col + 1];
            v.z = acc[i][j + 2] + bias[col + 2];
            v.w = acc[i][j + 3] + bias[col + 3];
            *(float4*)&C[row * N + col] = v;
        }
    }
}

// ---------------------------------------------------------------------------
// Phase 2: persistent LSTM recurrence.
// grid = 128 CTAs (blockIdx.x = g*RC + r), 256 threads each.
// CTA (g, r): batches [g*8, g*8+8), hidden units [r*16, r*16+16)
//   -> 64 gate columns: global col = gate*256 + r*16 + u, gate in {i,f,g,o}.
// Each thread holds a 64-element k-slice of one Whh column in registers.
// Warp w (0..7): k-chunk q = w&3 (k0=q*64), local col c = ((w>>2)<<5)|lane.
// h exchanged through g_Hall; per-step barrier = monotonic atomic per group.
// ---------------------------------------------------------------------------
__global__ __launch_bounds__(256, 1) void lstm_kernel(
    const float* __restrict__ c0, const float* __restrict__ h0,
    const float* __restrict__ Whh)
{
    const int g    = blockIdx.x / RC;
    const int r    = blockIdx.x % RC;
    const int tid  = threadIdx.x;
    const int wid  = tid >> 5, lane = tid & 31;
    const int q    = wid & 3;
    const int c    = ((wid >> 2) << 5) | lane;     // 0..63
    const int k0   = q * 64;
    const int gate = c >> 4, u = c & 15;
    const int gcol = gate * 256 + r * HU + u;

    __shared__ float h_smem[GB][HH];       // 8 KB: h_{t-1} for 8 batches
    __shared__ float red[4][GB][64];       // 8 KB: per-k-chunk partials

    // Load my Whh column slice into registers (one-time)
    float w[64];
#pragma unroll
    for (int i = 0; i < 64; i++)
        w[i] = Whh[(size_t)(k0 + i) * FH + gcol];

    // Init h_smem from h0
    for (int idx = tid; idx < GB * HH; idx += 256) {
        int b = idx >> 8, k = idx & 255;
        h_smem[b][k] = h0[(size_t)(g * GB + b) * HH + k];
    }

    // Reduce-thread state: tid<128 owns (rb, ru) = (batch, hidden unit), c in reg
    float creg = 0.f;
    int rb = 0, ru = 0;
    if (tid < 128) {
        rb = tid >> 4; ru = tid & 15;
        creg = c0[(size_t)(g * GB + rb) * HH + r * HU + ru];
    }
    __syncthreads();

    unsigned target = 0;

    for (int t = 0; t < TT; t++) {
        // Prefetch this step's precomputed gate contributions (x@Wih + bh)
        float pgi = 0.f, pgf = 0.f, pgg = 0.f, pgo = 0.f;
        if (tid < 128) {
            size_t base = ((size_t)(g * GB + rb) * TT + t) * FH + r * HU + ru;
            pgi = g_G[base];
            pgf = g_G[base + 256];
            pgg = g_G[base + 512];
            pgo = g_G[base + 768];
        }

        // GEMV partials: red[q][b][c] = sum_{k in chunk q} h[b][k] * Whh[k][gcol]
#pragma unroll
        for (int b = 0; b < GB; b++) {
            const float4* hp = (const float4*)&h_smem[b][k0];
            float s0 = 0.f, s1 = 0.f;
#pragma unroll
            for (int i = 0; i < 16; i += 2) {
                float4 hv0 = hp[i];
                float4 hv1 = hp[i + 1];
                s0 = fmaf(hv0.x, w[4 * i + 0], s0);
                s0 = fmaf(hv0.y, w[4 * i + 1], s0);
                s0 = fmaf(hv0.z, w[4 * i + 2], s0);
                s0 = fmaf(hv0.w, w[4 * i + 3], s0);
                s1 = fmaf(hv1.x, w[4 * i + 4], s1);
                s1 = fmaf(hv1.y, w[4 * i + 5], s1);
                s1 = fmaf(hv1.z, w[4 * i + 6], s1);
                s1 = fmaf(hv1.w, w[4 * i + 7], s1);
            }
            red[q][b][c] = s0 + s1;
        }
        __syncthreads();

        // Reduce across 4 k-chunks + pointwise LSTM cell (tid < 128)
        if (tid < 128) {
            float vi = pgi + red[0][rb][u]      + red[1][rb][u]      + red[2][rb][u]      + red[3][rb][u];
            float vf = pgf + red[0][rb][16 + u] + red[1][rb][16 + u] + red[2][rb][16 + u] + red[3][rb][16 + u];
            float vg = pgg + red[0][rb][32 + u] + red[1][rb][32 + u] + red[2][rb][32 + u] + red[3][rb][32 + u];
            float vo = pgo + red[0][rb][48 + u] + red[1][rb][48 + u] + red[2][rb][48 + u] + red[3][rb][48 + u];

            float ig = 1.f / (1.f + __expf(-vi));
            float fg = 1.f / (1.f + __expf(-vf));
            float gg = tanhf(vg);
            float og = 1.f / (1.f + __expf(-vo));

            creg = fg * creg + ig * gg;
            float hh = og * tanhf(creg);

            g_Hall[((size_t)(g * GB + rb) * TT + t) * HH + r * HU + ru] = hh;
            __threadfence();   // make my h visible before the barrier signal
        }
        __syncthreads();

        // Batch-group barrier: monotonic counter, 16 arrivals per step
        target += RC;
        if (tid == 0) {
            atomicAdd(&g_ctr[g], 1u);
            volatile unsigned* p = &g_ctr[g];
            while (*p < target) { }
            __threadfence();
        }
        __syncthreads();

        // Reload the full h_t (all 256 units from the 16 peer CTAs)
        {
            int b  = tid >> 5;
            int kk = (tid & 31) * 8;
            const float4* src =
                (const float4*)&g_Hall[((size_t)(g * GB + b) * TT + t) * HH + kk];
            float4 v0 = src[0], v1 = src[1];
            *(float4*)&h_smem[b][kk]     = v0;
            *(float4*)&h_smem[b][kk + 4] = v1;
        }
        __syncthreads();
    }
}

// ---------------------------------------------------------------------------
// Launch: init -> G = x@Wih + bh -> LSTM recurrence -> Y = Hall@Wout + bout
// Inputs (metadata order): x, c0, h0, Wih, Whh, bh, Wout, bout
// ---------------------------------------------------------------------------
extern "C" void kernel_launch(void* const* d_in, const int* in_sizes, int n_in,
                              void* d_out, int out_size)
{
    const float* x    = (const float*)d_in[0];
    const float* c0   = (const float*)d_in[1];
    const float* h0   = (const float*)d_in[2];
    const float* Wih  = (const float*)d_in[3];
    const float* Whh  = (const float*)d_in[4];
    const float* bh   = (const float*)d_in[5];
    const float* Wout = (const float*)d_in[6];
    const float* bout = (const float*)d_in[7];
    float* Y = (float*)d_out;

    float* Gp = nullptr;
    float* Hp = nullptr;
    cudaGetSymbolAddress((void**)&Gp, g_G);
    cudaGetSymbolAddress((void**)&Hp, g_Hall);

    init_kernel<<<1, 32>>>();

    // Phase 1: G[B*T, 4H] = x[B*T, D] @ Wih[D, 4H] + bh
    {
        dim3 grid(FH / 128, (BB * TT) / 128);
        gemm_kernel<<<grid, 256>>>(x, Wih, bh, Gp, BB * TT, FH, DD);
    }

    // Phase 2: sequential LSTM over T steps (persistent, 128 CTAs)
    lstm_kernel<<<NGRP * RC, 256>>>(c0, h0, Whh);

    // Phase 3: Y[B*T, O] = Hall[B*T, H] @ Wout[H, O] + bout
    {
        dim3 grid(OO / 128, (BB * TT) / 128);
        gemm_kernel<<<grid, 256>>>(Hp, Wout, bout, Y, BB * TT, OO, HH);
    }
}